// round 15
// baseline (speedup 1.0000x reference)
#include <cuda_runtime.h>

#define DIM 32768
#define NTOK 32
#define NPQC 60

typedef unsigned long long ull;

// ----------------------------------------------------------- f32x2 helpers --
__device__ __forceinline__ ull f2_mul(ull a, ull b) {
    ull d; asm("mul.rn.f32x2 %0,%1,%2;" : "=l"(d) : "l"(a), "l"(b)); return d;
}
__device__ __forceinline__ ull f2_fma(ull a, ull b, ull c) {
    ull d; asm("fma.rn.f32x2 %0,%1,%2,%3;" : "=l"(d) : "l"(a), "l"(b), "l"(c)); return d;
}
__device__ __forceinline__ ull f2_pack(float x, float y) {
    ull d; asm("mov.b64 %0,{%1,%2};" : "=l"(d) : "f"(x), "f"(y)); return d;
}
__device__ __forceinline__ ull f2_swap(ull v) {
    ull d;
    asm("{\n\t.reg .b32 lo,hi;\n\tmov.b64 {lo,hi},%1;\n\tmov.b64 %0,{hi,lo};\n\t}"
        : "=l"(d) : "l"(v));
    return d;
}

__device__ __forceinline__ unsigned smem_u32(const void* p) {
    unsigned a;
    asm("{ .reg .u64 t; cvta.to.shared.u64 t, %1; cvt.u32.u64 %0, t; }"
        : "=r"(a) : "l"(p));
    return a;
}

// DSMEM read: map own-shared address into peer CTA rank, 64-bit load.
__device__ __forceinline__ ull dsmem_ld(unsigned addr, int rank) {
    unsigned pa; ull v;
    asm("mapa.shared::cluster.u32 %0, %1, %2;" : "=r"(pa) : "r"(addr), "r"(rank));
    asm("ld.shared::cluster.b64 %0, [%1];" : "=l"(v) : "r"(pa));
    return v;
}

// Cluster-wide barrier with global-memory ordering.
__device__ __forceinline__ void cluster_bar() {
    asm volatile("fence.acq_rel.gpu;" ::: "memory");
    asm volatile("barrier.cluster.arrive.aligned;" ::: "memory");
    asm volatile("barrier.cluster.wait.aligned;" ::: "memory");
}

// Cluster barrier only (smem scope).
__device__ __forceinline__ void cluster_sync() {
    asm volatile("barrier.cluster.arrive.aligned;" ::: "memory");
    asm volatile("barrier.cluster.wait.aligned;" ::: "memory");
}

// ------------------------------------------------------------- gate encode --
__host__ __device__ constexpr int RYg(int p, int t) { return p | (t << 8) | (255 << 16); }
__host__ __device__ constexpr int CXg(int p, int t, int c) { return p | (t << 8) | (c << 16); }

__host__ __device__ constexpr int swz_c(int j) {
    return j ^ ((j >> 4) & 15) ^ ((j >> 8) & 15);
}
__host__ __device__ constexpr int gslot(int gmask, int n) {
    int c = 0;
    for (int s = 0; s < 12; ++s)
        if (gmask & (1 << s)) { if (c == n) return s; ++c; }
    return 0;
}
__host__ __device__ constexpr int spread4(int gmask, int m) {
    return ((m & 1) << gslot(gmask, 0)) | (((m >> 1) & 1) << gslot(gmask, 1))
         | (((m >> 2) & 1) << gslot(gmask, 2)) | (((m >> 3) & 1) << gslot(gmask, 3));
}

__device__ float2 g_cs[NTOK * NPQC];
__device__ float2 g_cs_ff[NPQC];
__device__ float2 g_lcu[NTOK];
__device__ float2 g_tok[NTOK * DIM];
__device__ float2 g_m1[DIM];
__device__ float2 g_m2[DIM];
__device__ float2 g_acc[DIM];

// ---------------------------------------------------------------- setup ----
// One warp per dot product; grid = ceil((NTOK*NPQC+3)/8) blocks of 256.
__global__ void setup_kernel(const float* __restrict__ emb,
                             const float* __restrict__ W,
                             const float* __restrict__ bias,
                             const float* __restrict__ lcu_ri,
                             const float* __restrict__ ffp) {
    int wid = threadIdx.x >> 5, lane = threadIdx.x & 31;
    int job = blockIdx.x * 8 + wid;
    if (job < NTOK * NPQC) {
        int t = job / NPQC, j = job % NPQC;
        const float4* e = (const float4*)(emb + t * 1024);
        const float4* w = (const float4*)(W + j * 1024);
        float p = 0.f;
        #pragma unroll
        for (int k = lane; k < 256; k += 32) {
            float4 a = e[k], b = w[k];
            p += a.x * b.x + a.y * b.y + a.z * b.z + a.w * b.w;
        }
        #pragma unroll
        for (int o = 16; o > 0; o >>= 1) p += __shfl_xor_sync(0xffffffffu, p, o);
        if (lane == 0) {
            float h = 0.5f * (p + bias[j]);
            g_cs[job] = make_float2(cosf(h), sinf(h));
        }
    } else if (job < NTOK * NPQC + 2) {
        int j = (job - NTOK * NPQC) * 32 + lane;
        if (j < NPQC) {
            float h = 0.5f * ffp[j];
            g_cs_ff[j] = make_float2(cosf(h), sinf(h));
        }
    } else if (job == NTOK * NPQC + 2) {
        float re = lcu_ri[2 * lane], im = lcu_ri[2 * lane + 1];
        float mag = sqrtf(re * re + im * im);
        float su = mag;
        #pragma unroll
        for (int o = 16; o > 0; o >>= 1) su += __shfl_xor_sync(0xffffffffu, su, o);
        su = fmaxf(su, 1e-8f);
        g_lcu[lane] = make_float2(re / su, im / su);
    }
}

// ------------------------------------------------------------ pass machinery --
template <int PASS>
__device__ __forceinline__ int amap(int c, int j) {
    if (PASS == 1 || PASS == 4) return j | (c << 12);
    if (PASS == 2) return (j & 511) | (c << 9) | ((j >> 9) << 12);
    return (j & 31) | (c << 5) | ((j >> 5) << 8);  // PASS 3
}

// Apply one compile-time-encoded gate to the 16 register amps.
template <int GMASK, int ENC>
__device__ __forceinline__ void apply_one(ull* a, const float2* __restrict__ cs,
                                          int c, int base) {
    constexpr int P = ENC & 255;
    constexpr int TGT = (ENC >> 8) & 255;
    constexpr int CTRL = (ENC >> 16) & 255;
    constexpr int S0 = gslot(GMASK, 0), S1 = gslot(GMASK, 1);
    constexpr int S2 = gslot(GMASK, 2), S3 = gslot(GMASK, 3);
    constexpr int Q = (TGT == S0) ? 0 : (TGT == S1) ? 1 : (TGT == S2) ? 2 : 3;

    float2 v = cs[P];
    if constexpr (CTRL == 255) {  // RY, packed f32x2
        ull cc2 = f2_pack(v.x, v.x);
        ull ss2 = f2_pack(v.y, v.y);
        ull ns2 = f2_pack(-v.y, -v.y);
        #pragma unroll
        for (int m = 0; m < 8; ++m) {
            int i0 = ((m >> Q) << (Q + 1)) | (m & ((1 << Q) - 1));
            int i1 = i0 | (1 << Q);
            ull t0 = f2_fma(cc2, a[i0], f2_mul(ns2, a[i1]));
            a[i1]  = f2_fma(cc2, a[i1], f2_mul(ss2, a[i0]));
            a[i0]  = t0;
        }
    } else {  // controlled-RX: n0 = cc*a0 + (ss,-ss)*swap(a1), n1 symmetric
        constexpr bool inG = (CTRL < 16) && ((GMASK >> CTRL) & 1);
        constexpr int CPOS = inG ? ((CTRL == S0) ? 0 : (CTRL == S1) ? 1
                                  : (CTRL == S2) ? 2 : 3) : -1;
        bool on = true;
        if constexpr (CTRL >= 16) on = (c >> (CTRL - 16)) & 1;
        else if constexpr (!inG)  on = (base >> CTRL) & 1;
        if (on) {
            ull cc2 = f2_pack(v.x, v.x);
            ull ssn = f2_pack(v.y, -v.y);
            #pragma unroll
            for (int m = 0; m < 8; ++m) {
                int i0 = ((m >> Q) << (Q + 1)) | (m & ((1 << Q) - 1));
                int i1 = i0 | (1 << Q);
                if (CPOS >= 0 && !((i0 >> CPOS) & 1)) continue;  // folds
                ull n0 = f2_fma(cc2, a[i0], f2_mul(ssn, f2_swap(a[i1])));
                ull n1 = f2_fma(cc2, a[i1], f2_mul(ssn, f2_swap(a[i0])));
                a[i0] = n0;
                a[i1] = n1;
            }
        }
    }
}

// One round: gather 16 amps, apply gates (compile-time list), scatter, sync.
template <int GMASK, int... ENCS>
__device__ __forceinline__ void do_round(float2* s, const float2* __restrict__ cs,
                                         int c) {
    int base = 0;
    {
        int t = threadIdx.x;
        #pragma unroll
        for (int sl = 0; sl < 12; ++sl)
            if (!((GMASK >> sl) & 1)) { base |= (t & 1) << sl; t >>= 1; }
    }
    int sb = swz_c(base);
    ull* s64 = reinterpret_cast<ull*>(s);

    ull a[16];
    #pragma unroll
    for (int m = 0; m < 16; ++m)
        a[m] = s64[sb ^ swz_c(spread4(GMASK, m))];

    (apply_one<GMASK, ENCS>(a, cs, c, base), ...);

    #pragma unroll
    for (int m = 0; m < 16; ++m)
        s64[sb ^ swz_c(spread4(GMASK, m))] = a[m];
    __syncthreads();
}

template <int PASS>
__device__ __forceinline__ void run_rounds(float2* s, const float2* __restrict__ cs,
                                           int c) {
    if constexpr (PASS == 1) {
        do_round<0xF00, RYg(3,11), RYg(4,10), RYg(5,9), RYg(6,8)>(s, cs, c);
        do_round<0x0F0, RYg(7,7), RYg(8,6), RYg(9,5), RYg(10,4)>(s, cs, c);
        do_round<0x00F, RYg(11,3), RYg(12,2), RYg(13,1), RYg(14,0)>(s, cs, c);
    } else if constexpr (PASS == 2) {
        do_round<0xF00, RYg(2,9), RYg(1,10), RYg(0,11)>(s, cs, c);
        do_round<0x807, CXg(15,11,0), CXg(16,0,1), CXg(17,1,2), CXg(18,2,3)>(s, cs, c);
        do_round<0x078, CXg(19,3,4), CXg(20,4,5), CXg(21,5,6), CXg(22,6,7)>(s, cs, c);
        do_round<0x780, CXg(23,7,8), CXg(24,8,16)>(s, cs, c);
    } else if constexpr (PASS == 3) {
        do_round<0x3C0, CXg(25,6,7), CXg(26,7,8), CXg(27,8,9), CXg(28,9,10)>(s, cs, c);
        do_round<0xF00, CXg(29,10,11), RYg(30,11), RYg(31,10), RYg(32,9), RYg(33,8)>(s, cs, c);
        do_round<0x0F0, RYg(34,7), RYg(35,6), RYg(36,5), RYg(40,4)>(s, cs, c);
        do_round<0x00F, RYg(41,3), RYg(42,2), RYg(43,1), RYg(44,0), CXg(45,1,0)>(s, cs, c);
        do_round<0xE01, CXg(46,0,11), CXg(47,11,10), CXg(48,10,9), CXg(49,9,8)>(s, cs, c);
        do_round<0x1E0, CXg(50,8,7), CXg(51,7,6), CXg(52,6,5)>(s, cs, c);
    } else {
        do_round<0x1E0, RYg(37,7), RYg(38,6), RYg(39,5),
                 CXg(53,8,7), CXg(54,7,6), CXg(55,6,5), CXg(56,5,4)>(s, cs, c);
        do_round<0x01E, CXg(57,4,3), CXg(58,3,2), CXg(59,2,1)>(s, cs, c);
    }
}

// Exchange: write current pass layout to g_tok, cluster-sync, read next layout.
template <int PW, int PR>
__device__ __forceinline__ void exchange(float2* s, float2* dp, int c) {
    #pragma unroll 4
    for (int j = threadIdx.x; j < 4096; j += 256)
        __stcg(&dp[amap<PW>(c, j)], s[swz_c(j)]);
    cluster_bar();
    #pragma unroll 4
    for (int j = threadIdx.x; j < 4096; j += 256)
        s[swz_c(j)] = __ldcg(&dp[amap<PR>(c, j)]);
    __syncthreads();
}

// One full stage (4 passes) per launch; 8 chunk-CTAs of a token = 1 cluster.
// SRCSEL: 0 = e0, 2 = g_m1, 3 = g_m2.
template <int SRCSEL>
__global__ void __launch_bounds__(256) __cluster_dims__(8, 1, 1)
stage_kernel() {
    __shared__ float2 s[4096];
    int c = blockIdx.x;
    int t = blockIdx.y;
    const float2* cs = g_cs + t * NPQC;
    float2* dp = g_tok + (size_t)t * DIM;

    if constexpr (SRCSEL == 0) {
        for (int j = threadIdx.x; j < 4096; j += 256) {
            int i = amap<1>(c, j);
            s[swz_c(j)] = make_float2(i == 0 ? 1.f : 0.f, 0.f);
        }
    } else {
        const float2* sp = (SRCSEL == 2) ? g_m1 : g_m2;
        #pragma unroll 4
        for (int j = threadIdx.x; j < 4096; j += 256)
            s[swz_c(j)] = __ldcg(&sp[amap<1>(c, j)]);
    }
    __syncthreads();

    run_rounds<1>(s, cs, c);
    exchange<1, 2>(s, dp, c);
    run_rounds<2>(s, cs, c);
    exchange<2, 3>(s, dp, c);
    run_rounds<3>(s, cs, c);
    exchange<3, 4>(s, dp, c);
    run_rounds<4>(s, cs, c);

    #pragma unroll 4
    for (int j = threadIdx.x; j < 4096; j += 256)
        __stcg(&dp[amap<4>(c, j)], s[swz_c(j)]);
}

// ---------------------------------------------------------------- reduce ----
__global__ void reduce_kernel(int out_sel, const float* __restrict__ qsvt) {
    int i = blockIdx.x * blockDim.x + threadIdx.x;
    float2 a = make_float2(0.f, 0.f);
    #pragma unroll
    for (int t = 0; t < NTOK; ++t) {
        float2 l = g_lcu[t];
        float2 v = __ldcg(&g_tok[t * DIM + i]);
        a.x += v.x * l.x - v.y * l.y;
        a.y += v.x * l.y + v.y * l.x;
    }
    if (out_sel == 1) {
        g_m1[i] = a;
    } else if (out_sel == 2) {
        g_m2[i] = a;
    } else {
        float q0 = qsvt[0], q1 = qsvt[1], q2 = qsvt[2], q3 = qsvt[3];
        float2 b1 = g_m1[i], b2 = g_m2[i];
        float2 o;
        o.x = q1 * b1.x + q2 * b2.x + q3 * a.x + (i == 0 ? q0 : 0.f);
        o.y = q1 * b1.y + q2 * b2.y + q3 * a.y;
        g_acc[i] = o;
    }
}

// ----------------------------------------- final evolve + measure (1 cluster) --
__device__ __forceinline__ float block_sum(float v, float* buf) {
    int wid = threadIdx.x >> 5, lane = threadIdx.x & 31;
    #pragma unroll
    for (int o = 16; o > 0; o >>= 1) v += __shfl_xor_sync(0xffffffffu, v, o);
    if (lane == 0) buf[wid] = v;
    __syncthreads();
    float r = 0.f;
    if (threadIdx.x == 0) {
        #pragma unroll
        for (int w = 0; w < 8; ++w) r += buf[w];
    }
    __syncthreads();
    return r;  // valid on thread 0 only
}

__global__ void __cluster_dims__(8, 1, 1)
final_kernel(float* __restrict__ out) {
    __shared__ float2 s[4096];
    __shared__ float redbuf[8];
    int c = blockIdx.x;
    int tid = threadIdx.x;
    const float2* cs = g_cs_ff;
    float2* dp = g_tok;  // token-0 slot as exchange scratch
    float* scratch = reinterpret_cast<float*>(g_m1);  // free after stage 2

    // ---- final evolve (same 4-pass body as stage_kernel, src = g_acc) ----
    #pragma unroll 4
    for (int j = tid; j < 4096; j += 256)
        s[swz_c(j)] = __ldcg(&g_acc[amap<1>(c, j)]);
    __syncthreads();

    run_rounds<1>(s, cs, c);
    exchange<1, 2>(s, dp, c);
    run_rounds<2>(s, cs, c);
    exchange<2, 3>(s, dp, c);
    run_rounds<3>(s, cs, c);
    exchange<3, 4>(s, dp, c);
    run_rounds<4>(s, cs, c);
    // tile now holds chunk c in layout amap<4> (global i = j | c<<12)

    cluster_sync();  // all tiles complete before peer reads

    // ---- measure: local bits 0..11 (pairs inside the tile) + n_c ----
    float n_thr = 0.f;
    for (int b = 0; b < 12; ++b) {
        float x = 0.f, y = 0.f, z = 0.f;
        int lowmask = (1 << b) - 1;
        for (int p = tid; p < 2048; p += 256) {
            int j0 = ((p >> b) << (b + 1)) | (p & lowmask);
            int j1 = j0 | (1 << b);
            float2 a0 = s[swz_c(j0)], a1 = s[swz_c(j1)];
            x += a0.x * a1.x + a0.y * a1.y;
            y += a0.x * a1.y - a0.y * a1.x;
            float m0 = a0.x * a0.x + a0.y * a0.y;
            float m1 = a1.x * a1.x + a1.y * a1.y;
            z += m0 - m1;
            if (b == 0) n_thr += m0 + m1;
        }
        float X = block_sum(x, redbuf);
        float Y = block_sum(y, redbuf);
        float Z = block_sum(z, redbuf);
        if (tid == 0) {
            __stcg(&scratch[c * 64 + b], X);
            __stcg(&scratch[c * 64 + 15 + b], Y);
            __stcg(&scratch[c * 64 + 30 + b], Z);
        }
    }
    {
        float N = block_sum(n_thr, redbuf);
        if (tid == 0) __stcg(&scratch[c * 64 + 42], N);
    }

    // ---- measure: chunk bits 12..14 (x,y via DSMEM peer reads) ----
    unsigned s32 = smem_u32(s);
    for (int b3 = 0; b3 < 3; ++b3) {
        float x = 0.f, y = 0.f;
        if (((c >> b3) & 1) == 0) {
            int peer = c | (1 << b3);
            for (int j = tid; j < 4096; j += 256) {
                float2 a0 = s[swz_c(j)];
                ull pv = dsmem_ld(s32 + (unsigned)swz_c(j) * 8u, peer);
                float2 a1; a1.x = __uint_as_float((unsigned)pv);
                a1.y = __uint_as_float((unsigned)(pv >> 32));
                x += a0.x * a1.x + a0.y * a1.y;
                y += a0.x * a1.y - a0.y * a1.x;
            }
        }
        float X = block_sum(x, redbuf);
        float Y = block_sum(y, redbuf);
        if (tid == 0) {
            __stcg(&scratch[c * 64 + 12 + b3], X);
            __stcg(&scratch[c * 64 + 27 + b3], Y);
        }
    }

    cluster_bar();  // scratch visible cluster-wide

    // ---- CTA 0: combine partials, write 45 outputs ----
    if (c == 0 && tid < 15) {
        int b = tid;
        float N = 0.f;
        #pragma unroll
        for (int cc = 0; cc < 8; ++cc) N += __ldcg(&scratch[cc * 64 + 42]);
        float X = 0.f, Y = 0.f, Z = 0.f;
        #pragma unroll
        for (int cc = 0; cc < 8; ++cc) {
            X += __ldcg(&scratch[cc * 64 + b]);
            Y += __ldcg(&scratch[cc * 64 + 15 + b]);
        }
        if (b < 12) {
            #pragma unroll
            for (int cc = 0; cc < 8; ++cc) Z += __ldcg(&scratch[cc * 64 + 30 + b]);
        } else {
            int b3 = b - 12;
            #pragma unroll
            for (int cc = 0; cc < 8; ++cc) {
                float nc = __ldcg(&scratch[cc * 64 + 42]);
                Z += ((cc >> b3) & 1) ? -nc : nc;
            }
        }
        float inv = 1.f / fmaxf(N, 1e-20f);
        int w = 14 - b;
        out[w]      = 2.f * X * inv;
        out[15 + w] = 2.f * Y * inv;
        out[30 + w] = Z * inv;
    }
}

// ---------------------------------------------------------------- launch ----
extern "C" void kernel_launch(void* const* d_in, const int* in_sizes, int n_in,
                              void* d_out, int out_size) {
    (void)in_sizes; (void)n_in; (void)out_size;
    const float* emb  = (const float*)d_in[0];
    const float* W    = (const float*)d_in[1];
    const float* bias = (const float*)d_in[2];
    const float* qsvt = (const float*)d_in[3];
    const float* lcu  = (const float*)d_in[4];
    const float* ffp  = (const float*)d_in[5];
    float* out = (float*)d_out;

    setup_kernel<<<(NTOK * NPQC + 3 + 7) / 8, 256>>>(emb, W, bias, lcu, ffp);

    dim3 gs(8, NTOK);   // 8 chunks x 32 tokens (8-CTA clusters along x)
    dim3 gf(8, 1);      // final evolve + measure: one cluster

    stage_kernel<0><<<gs, 256>>>();                   // stage 1 (input = e0)
    reduce_kernel<<<DIM / 256, 256>>>(1, nullptr);
    stage_kernel<2><<<gs, 256>>>();                   // stage 2 (input = m1)
    reduce_kernel<<<DIM / 256, 256>>>(2, nullptr);
    stage_kernel<3><<<gs, 256>>>();                   // stage 3 (input = m2)
    reduce_kernel<<<DIM / 256, 256>>>(3, qsvt);
    final_kernel<<<gf, 256>>>(out);                   // final evolve + measure
}

// round 16
// speedup vs baseline: 1.0847x; 1.0847x over previous
#include <cuda_runtime.h>

#define DIM 32768
#define NTOK 32
#define NPQC 60

typedef unsigned long long ull;

// ----------------------------------------------------------- f32x2 helpers --
__device__ __forceinline__ ull f2_mul(ull a, ull b) {
    ull d; asm("mul.rn.f32x2 %0,%1,%2;" : "=l"(d) : "l"(a), "l"(b)); return d;
}
__device__ __forceinline__ ull f2_fma(ull a, ull b, ull c) {
    ull d; asm("fma.rn.f32x2 %0,%1,%2,%3;" : "=l"(d) : "l"(a), "l"(b), "l"(c)); return d;
}
__device__ __forceinline__ ull f2_pack(float x, float y) {
    ull d; asm("mov.b64 %0,{%1,%2};" : "=l"(d) : "f"(x), "f"(y)); return d;
}
__device__ __forceinline__ ull f2_swap(ull v) {
    ull d;
    asm("{\n\t.reg .b32 lo,hi;\n\tmov.b64 {lo,hi},%1;\n\tmov.b64 %0,{hi,lo};\n\t}"
        : "=l"(d) : "l"(v));
    return d;
}

// Cluster-wide barrier with global-memory ordering.
__device__ __forceinline__ void cluster_bar() {
    asm volatile("fence.acq_rel.gpu;" ::: "memory");
    asm volatile("barrier.cluster.arrive.aligned;" ::: "memory");
    asm volatile("barrier.cluster.wait.aligned;" ::: "memory");
}

// ------------------------------------------------------------- gate encode --
__host__ __device__ constexpr int RYg(int p, int t) { return p | (t << 8) | (255 << 16); }
__host__ __device__ constexpr int CXg(int p, int t, int c) { return p | (t << 8) | (c << 16); }

__host__ __device__ constexpr int swz_c(int j) {
    return j ^ ((j >> 4) & 15) ^ ((j >> 8) & 15);
}
__host__ __device__ constexpr int gslot(int gmask, int n) {
    int c = 0;
    for (int s = 0; s < 12; ++s)
        if (gmask & (1 << s)) { if (c == n) return s; ++c; }
    return 0;
}
__host__ __device__ constexpr int spread4(int gmask, int m) {
    return ((m & 1) << gslot(gmask, 0)) | (((m >> 1) & 1) << gslot(gmask, 1))
         | (((m >> 2) & 1) << gslot(gmask, 2)) | (((m >> 3) & 1) << gslot(gmask, 3));
}

__device__ float2 g_cs[NTOK * NPQC];
__device__ float2 g_cs_ff[NPQC];
__device__ float2 g_lcu[NTOK];
__device__ float2 g_tok[NTOK * DIM];
__device__ float2 g_m1[DIM];
__device__ float2 g_m2[DIM];
__device__ float2 g_acc[DIM];

// ---------------------------------------------------------------- setup ----
// One warp per dot product; grid = ceil((NTOK*NPQC+3)/8) blocks of 256.
__global__ void setup_kernel(const float* __restrict__ emb,
                             const float* __restrict__ W,
                             const float* __restrict__ bias,
                             const float* __restrict__ lcu_ri,
                             const float* __restrict__ ffp) {
    int wid = threadIdx.x >> 5, lane = threadIdx.x & 31;
    int job = blockIdx.x * 8 + wid;
    if (job < NTOK * NPQC) {
        int t = job / NPQC, j = job % NPQC;
        const float4* e = (const float4*)(emb + t * 1024);
        const float4* w = (const float4*)(W + j * 1024);
        float p = 0.f;
        #pragma unroll
        for (int k = lane; k < 256; k += 32) {
            float4 a = e[k], b = w[k];
            p += a.x * b.x + a.y * b.y + a.z * b.z + a.w * b.w;
        }
        #pragma unroll
        for (int o = 16; o > 0; o >>= 1) p += __shfl_xor_sync(0xffffffffu, p, o);
        if (lane == 0) {
            float h = 0.5f * (p + bias[j]);
            g_cs[job] = make_float2(cosf(h), sinf(h));
        }
    } else if (job < NTOK * NPQC + 2) {
        int j = (job - NTOK * NPQC) * 32 + lane;
        if (j < NPQC) {
            float h = 0.5f * ffp[j];
            g_cs_ff[j] = make_float2(cosf(h), sinf(h));
        }
    } else if (job == NTOK * NPQC + 2) {
        float re = lcu_ri[2 * lane], im = lcu_ri[2 * lane + 1];
        float mag = sqrtf(re * re + im * im);
        float su = mag;
        #pragma unroll
        for (int o = 16; o > 0; o >>= 1) su += __shfl_xor_sync(0xffffffffu, su, o);
        su = fmaxf(su, 1e-8f);
        g_lcu[lane] = make_float2(re / su, im / su);
    }
}

// ------------------------------------------------------------ pass kernel ----
template <int PASS>
__device__ __forceinline__ int amap(int c, int j) {
    if (PASS == 1 || PASS == 4) return j | (c << 12);
    if (PASS == 2) return (j & 511) | (c << 9) | ((j >> 9) << 12);
    return (j & 31) | (c << 5) | ((j >> 5) << 8);  // PASS 3
}

// Apply one compile-time-encoded gate to the 16 register amps.
template <int GMASK, int ENC>
__device__ __forceinline__ void apply_one(ull* a, const float2* __restrict__ cs,
                                          int c, int base) {
    constexpr int P = ENC & 255;
    constexpr int TGT = (ENC >> 8) & 255;
    constexpr int CTRL = (ENC >> 16) & 255;
    constexpr int S0 = gslot(GMASK, 0), S1 = gslot(GMASK, 1);
    constexpr int S2 = gslot(GMASK, 2), S3 = gslot(GMASK, 3);
    constexpr int Q = (TGT == S0) ? 0 : (TGT == S1) ? 1 : (TGT == S2) ? 2 : 3;

    float2 v = cs[P];
    if constexpr (CTRL == 255) {  // RY, packed f32x2
        ull cc2 = f2_pack(v.x, v.x);
        ull ss2 = f2_pack(v.y, v.y);
        ull ns2 = f2_pack(-v.y, -v.y);
        #pragma unroll
        for (int m = 0; m < 8; ++m) {
            int i0 = ((m >> Q) << (Q + 1)) | (m & ((1 << Q) - 1));
            int i1 = i0 | (1 << Q);
            ull t0 = f2_fma(cc2, a[i0], f2_mul(ns2, a[i1]));
            a[i1]  = f2_fma(cc2, a[i1], f2_mul(ss2, a[i0]));
            a[i0]  = t0;
        }
    } else {  // controlled-RX: n0 = cc*a0 + (ss,-ss)*swap(a1), n1 symmetric
        constexpr bool inG = (CTRL < 16) && ((GMASK >> CTRL) & 1);
        constexpr int CPOS = inG ? ((CTRL == S0) ? 0 : (CTRL == S1) ? 1
                                  : (CTRL == S2) ? 2 : 3) : -1;
        bool on = true;
        if constexpr (CTRL >= 16) on = (c >> (CTRL - 16)) & 1;
        else if constexpr (!inG)  on = (base >> CTRL) & 1;
        if (on) {
            ull cc2 = f2_pack(v.x, v.x);
            ull ssn = f2_pack(v.y, -v.y);
            #pragma unroll
            for (int m = 0; m < 8; ++m) {
                int i0 = ((m >> Q) << (Q + 1)) | (m & ((1 << Q) - 1));
                int i1 = i0 | (1 << Q);
                if (CPOS >= 0 && !((i0 >> CPOS) & 1)) continue;  // folds
                ull n0 = f2_fma(cc2, a[i0], f2_mul(ssn, f2_swap(a[i1])));
                ull n1 = f2_fma(cc2, a[i1], f2_mul(ssn, f2_swap(a[i0])));
                a[i0] = n0;
                a[i1] = n1;
            }
        }
    }
}

// One round: gather 16 amps, apply gates (compile-time list), scatter, sync.
template <int GMASK, int... ENCS>
__device__ __forceinline__ void do_round(float2* s, const float2* __restrict__ cs,
                                         int c) {
    int base = 0;
    {
        int t = threadIdx.x;
        #pragma unroll
        for (int sl = 0; sl < 12; ++sl)
            if (!((GMASK >> sl) & 1)) { base |= (t & 1) << sl; t >>= 1; }
    }
    int sb = swz_c(base);
    ull* s64 = reinterpret_cast<ull*>(s);

    ull a[16];
    #pragma unroll
    for (int m = 0; m < 16; ++m)
        a[m] = s64[sb ^ swz_c(spread4(GMASK, m))];

    (apply_one<GMASK, ENCS>(a, cs, c, base), ...);

    #pragma unroll
    for (int m = 0; m < 16; ++m)
        s64[sb ^ swz_c(spread4(GMASK, m))] = a[m];
    __syncthreads();
}

template <int PASS>
__device__ __forceinline__ void run_rounds(float2* s, const float2* __restrict__ cs,
                                           int c) {
    if constexpr (PASS == 1) {
        do_round<0xF00, RYg(3,11), RYg(4,10), RYg(5,9), RYg(6,8)>(s, cs, c);
        do_round<0x0F0, RYg(7,7), RYg(8,6), RYg(9,5), RYg(10,4)>(s, cs, c);
        do_round<0x00F, RYg(11,3), RYg(12,2), RYg(13,1), RYg(14,0)>(s, cs, c);
    } else if constexpr (PASS == 2) {
        do_round<0xF00, RYg(2,9), RYg(1,10), RYg(0,11)>(s, cs, c);
        do_round<0x807, CXg(15,11,0), CXg(16,0,1), CXg(17,1,2), CXg(18,2,3)>(s, cs, c);
        do_round<0x078, CXg(19,3,4), CXg(20,4,5), CXg(21,5,6), CXg(22,6,7)>(s, cs, c);
        do_round<0x780, CXg(23,7,8), CXg(24,8,16)>(s, cs, c);
    } else if constexpr (PASS == 3) {
        do_round<0x3C0, CXg(25,6,7), CXg(26,7,8), CXg(27,8,9), CXg(28,9,10)>(s, cs, c);
        do_round<0xF00, CXg(29,10,11), RYg(30,11), RYg(31,10), RYg(32,9), RYg(33,8)>(s, cs, c);
        do_round<0x0F0, RYg(34,7), RYg(35,6), RYg(36,5), RYg(40,4)>(s, cs, c);
        do_round<0x00F, RYg(41,3), RYg(42,2), RYg(43,1), RYg(44,0), CXg(45,1,0)>(s, cs, c);
        do_round<0xE01, CXg(46,0,11), CXg(47,11,10), CXg(48,10,9), CXg(49,9,8)>(s, cs, c);
        do_round<0x1E0, CXg(50,8,7), CXg(51,7,6), CXg(52,6,5)>(s, cs, c);
    } else {
        do_round<0x1E0, RYg(37,7), RYg(38,6), RYg(39,5),
                 CXg(53,8,7), CXg(54,7,6), CXg(55,6,5), CXg(56,5,4)>(s, cs, c);
        do_round<0x01E, CXg(57,4,3), CXg(58,3,2), CXg(59,2,1)>(s, cs, c);
    }
}

// Exchange: write current pass layout to g_tok, cluster-sync, read next layout.
template <int PW, int PR>
__device__ __forceinline__ void exchange(float2* s, float2* dp, int c) {
    #pragma unroll 4
    for (int j = threadIdx.x; j < 4096; j += 256)
        __stcg(&dp[amap<PW>(c, j)], s[swz_c(j)]);
    cluster_bar();
    #pragma unroll 4
    for (int j = threadIdx.x; j < 4096; j += 256)
        s[swz_c(j)] = __ldcg(&dp[amap<PR>(c, j)]);
    __syncthreads();
}

// One full stage (4 passes) per launch; 8 chunk-CTAs of a token = 1 cluster.
// SRCSEL: 0 = e0, 2 = g_m1, 3 = g_m2, 4 = g_acc (final evolve, ff params).
template <int SRCSEL>
__global__ void __launch_bounds__(256) __cluster_dims__(8, 1, 1)
stage_kernel() {
    __shared__ float2 s[4096];
    int c = blockIdx.x;
    int t = blockIdx.y;
    const float2* cs = (SRCSEL == 4) ? g_cs_ff : (g_cs + t * NPQC);
    float2* dp = g_tok + (size_t)t * DIM;

    if constexpr (SRCSEL == 0) {
        for (int j = threadIdx.x; j < 4096; j += 256) {
            int i = amap<1>(c, j);
            s[swz_c(j)] = make_float2(i == 0 ? 1.f : 0.f, 0.f);
        }
    } else {
        const float2* sp = (SRCSEL == 2) ? g_m1 : (SRCSEL == 3) ? g_m2 : g_acc;
        #pragma unroll 4
        for (int j = threadIdx.x; j < 4096; j += 256)
            s[swz_c(j)] = __ldcg(&sp[amap<1>(c, j)]);
    }
    __syncthreads();

    run_rounds<1>(s, cs, c);
    exchange<1, 2>(s, dp, c);
    run_rounds<2>(s, cs, c);
    exchange<2, 3>(s, dp, c);
    run_rounds<3>(s, cs, c);
    exchange<3, 4>(s, dp, c);
    run_rounds<4>(s, cs, c);

    #pragma unroll 4
    for (int j = threadIdx.x; j < 4096; j += 256)
        __stcg(&dp[amap<4>(c, j)], s[swz_c(j)]);
}

// ---------------------------------------------------------------- reduce ----
__global__ void reduce_kernel(int out_sel, const float* __restrict__ qsvt) {
    int i = blockIdx.x * blockDim.x + threadIdx.x;
    float2 a = make_float2(0.f, 0.f);
    #pragma unroll
    for (int t = 0; t < NTOK; ++t) {
        float2 l = g_lcu[t];
        float2 v = __ldcg(&g_tok[t * DIM + i]);
        a.x += v.x * l.x - v.y * l.y;
        a.y += v.x * l.y + v.y * l.x;
    }
    if (out_sel == 1) {
        g_m1[i] = a;
    } else if (out_sel == 2) {
        g_m2[i] = a;
    } else {
        float q0 = qsvt[0], q1 = qsvt[1], q2 = qsvt[2], q3 = qsvt[3];
        float2 b1 = g_m1[i], b2 = g_m2[i];
        float2 o;
        o.x = q1 * b1.x + q2 * b2.x + q3 * a.x + (i == 0 ? q0 : 0.f);
        o.y = q1 * b1.y + q2 * b2.y + q3 * a.y;
        g_acc[i] = o;
    }
}

// --------------------------------------------------------------- measure ----
__global__ void measure_kernel(float* __restrict__ out) {
    const float2* st = g_tok;  // final state lives in token-0 slot
    int b = blockIdx.x;        // bit index 0..14 ; qubit w = 14 - b
    int tid = threadIdx.x;
    int lowmask = (1 << b) - 1;
    float x = 0.f, y = 0.f, z = 0.f, n = 0.f;
    for (int p = tid; p < DIM / 2; p += 256) {
        int i0 = ((p >> b) << (b + 1)) | (p & lowmask);
        int i1 = i0 | (1 << b);
        float2 a0 = __ldcg(&st[i0]), a1 = __ldcg(&st[i1]);
        x += a0.x * a1.x + a0.y * a1.y;
        y += a0.x * a1.y - a0.y * a1.x;
        float m0 = a0.x * a0.x + a0.y * a0.y;
        float m1 = a1.x * a1.x + a1.y * a1.y;
        z += m0 - m1;
        n += m0 + m1;
    }
    __shared__ float red[4 * 256];
    red[tid] = x; red[256 + tid] = y; red[512 + tid] = z; red[768 + tid] = n;
    __syncthreads();
    for (int s = 128; s > 0; s >>= 1) {
        if (tid < s) {
            red[tid]       += red[tid + s];
            red[256 + tid] += red[256 + tid + s];
            red[512 + tid] += red[512 + tid + s];
            red[768 + tid] += red[768 + tid + s];
        }
        __syncthreads();
    }
    if (tid == 0) {
        float inv = 1.f / fmaxf(red[768], 1e-20f);
        int w = 14 - b;
        out[w]      = 2.f * red[0]   * inv;
        out[15 + w] = 2.f * red[256] * inv;
        out[30 + w] = red[512] * inv;
    }
}

// ---------------------------------------------------------------- launch ----
extern "C" void kernel_launch(void* const* d_in, const int* in_sizes, int n_in,
                              void* d_out, int out_size) {
    (void)in_sizes; (void)n_in; (void)out_size;
    const float* emb  = (const float*)d_in[0];
    const float* W    = (const float*)d_in[1];
    const float* bias = (const float*)d_in[2];
    const float* qsvt = (const float*)d_in[3];
    const float* lcu  = (const float*)d_in[4];
    const float* ffp  = (const float*)d_in[5];
    float* out = (float*)d_out;

    setup_kernel<<<(NTOK * NPQC + 3 + 7) / 8, 256>>>(emb, W, bias, lcu, ffp);

    dim3 gs(8, NTOK);   // 8 chunks x 32 tokens (8-CTA clusters along x)
    dim3 gf(8, 1);      // final evolve: single state, one cluster

    stage_kernel<0><<<gs, 256>>>();                   // stage 1 (input = e0)
    reduce_kernel<<<DIM / 256, 256>>>(1, nullptr);
    stage_kernel<2><<<gs, 256>>>();                   // stage 2 (input = m1)
    reduce_kernel<<<DIM / 256, 256>>>(2, nullptr);
    stage_kernel<3><<<gs, 256>>>();                   // stage 3 (input = m2)
    reduce_kernel<<<DIM / 256, 256>>>(3, qsvt);
    stage_kernel<4><<<gf, 256>>>();                   // final evolve (ff params)
    measure_kernel<<<15, 256>>>(out);
}